// round 4
// baseline (speedup 1.0000x reference)
#include <cuda_runtime.h>

#define HWSZ 9216            // 96*96
#define NCH  128             // Cin = Cout = 128
#define NE   8               // experts
#define NEXP 9               // experts + shared
#define P_TOT 36864          // 4*96*96 pixels
#define KFULL 1152           // 128*9

typedef unsigned long long ull;

// ---------------- device scratch (no allocations allowed) ----------------
__device__ float g_wT[NEXP * KFULL * NCH];   // [e][k=ci*9+tap][co]  ~5.3 MB
__device__ int   g_cnt[16];
__device__ int   g_listP[NE * P_TOT];
__device__ float g_listW[NE * P_TOT];

// ---------------- packed f32x2 helpers (Blackwell FFMA2) ----------------
__device__ __forceinline__ ull ffma2(ull a, ull b, ull c) {
    ull d;
    asm("fma.rn.f32x2 %0, %1, %2, %3;" : "=l"(d) : "l"(a), "l"(b), "l"(c));
    return d;
}
__device__ __forceinline__ ull dup2(float x) {
    ull d;
    asm("mov.b64 %0, {%1, %1};" : "=l"(d) : "f"(x));
    return d;
}
__device__ __forceinline__ float2 unpack2(ull a) {
    float2 r;
    asm("mov.b64 {%0, %1}, %2;" : "=f"(r.x), "=f"(r.y) : "l"(a));
    return r;
}

// ---------------- prep: transpose weights + zero counters ----------------
__global__ void prep_kernel(const float* __restrict__ expert_w,
                            const float* __restrict__ shared_w) {
    int idx = blockIdx.x * 256 + threadIdx.x;
    if (idx < 16) g_cnt[idx] = 0;
    if (idx >= NEXP * KFULL * NCH) return;
    int co  = idx & 127;
    int k   = (idx >> 7) % KFULL;
    int e   = idx / (KFULL * NCH);
    int ci  = k / 9;
    int tap = k - ci * 9;
    float v;
    if (e < NE) v = expert_w[(((e * NCH + co) * NCH) + ci) * 9 + tap];
    else        v = shared_w[((co * NCH) + ci) * 9 + tap];
    g_wT[idx] = v;
}

// ---------------- gate: scores, top-2, softmax, lists, bias-init out ----------------
__global__ __launch_bounds__(256) void gate_kernel(
    const float* __restrict__ x, const float* __restrict__ gate_w,
    const float* __restrict__ gate_bias, const float* __restrict__ expert_b,
    const float* __restrict__ shared_b, float* __restrict__ out)
{
    __shared__ float gwS[NE * KFULL];       // 36864 B (all gate weights)
    __shared__ float xt[8 * 18 * 18];       // 10368 B (x halo tile, 8 ci)
    const int tid = threadIdx.x;
    const int tx = tid & 15, ty = tid >> 4;
    const int bx = blockIdx.x, by = blockIdx.y, b = blockIdx.z;

    for (int i = tid; i < NE * KFULL; i += 256) gwS[i] = gate_w[i];

    float acc[NE];
#pragma unroll
    for (int e = 0; e < NE; ++e) acc[e] = 0.f;

    const int h = by * 16 + ty, w = bx * 16 + tx;
    const float* xb = x + (long)b * (NCH * HWSZ);

    for (int cc = 0; cc < 16; ++cc) {             // 16 chunks of 8 ci
        __syncthreads();
        for (int i = tid; i < 8 * 324; i += 256) {
            int ci = i / 324; int r = i - ci * 324;
            int ly = r / 18;  int lx = r - ly * 18;
            int gh = by * 16 + ly - 1, gw = bx * 16 + lx - 1;
            float v = 0.f;
            if ((unsigned)gh < 96u && (unsigned)gw < 96u)
                v = xb[(cc * 8 + ci) * HWSZ + gh * 96 + gw];
            xt[i] = v;
        }
        __syncthreads();
#pragma unroll
        for (int ci = 0; ci < 8; ++ci) {
            float xn[9];
            const int base = ci * 324 + ty * 18 + tx;
#pragma unroll
            for (int r = 0; r < 3; ++r)
#pragma unroll
                for (int c2 = 0; c2 < 3; ++c2)
                    xn[r * 3 + c2] = xt[base + r * 18 + c2];
#pragma unroll
            for (int e = 0; e < NE; ++e) {
                const float* wp = &gwS[e * KFULL + (cc * 8 + ci) * 9];
                float a = acc[e];
#pragma unroll
                for (int t = 0; t < 9; ++t) a += wp[t] * xn[t];
                acc[e] = a;
            }
        }
    }

    // sigmoid + biased top-2 (first-index tie rule, matches jax top_k)
    float s[NE];
    float v0 = -1e30f, v1 = -1e30f; int i0 = 0, i1 = 1;
#pragma unroll
    for (int e = 0; e < NE; ++e) {
        float sv = 1.f / (1.f + expf(-acc[e]));
        s[e] = sv;
        float bv = sv + gate_bias[e];
        if (bv > v0)      { v1 = v0; i1 = i0; v0 = bv; i0 = e; }
        else if (bv > v1) { v1 = bv; i1 = e; }
    }
    // softmax over UNBIASED scores at top-2
    float s0 = s[i0], s1 = s[i1];
    float mx = fmaxf(s0, s1);
    float e0 = expf(s0 - mx), e1 = expf(s1 - mx);
    float inv = 1.f / (e0 + e1);
    float w0 = e0 * inv, w1 = e1 * inv;

    const int p = b * HWSZ + h * 96 + w;
    int sl0 = atomicAdd(&g_cnt[i0], 1);
    g_listP[i0 * P_TOT + sl0] = p; g_listW[i0 * P_TOT + sl0] = w0;
    int sl1 = atomicAdd(&g_cnt[i1], 1);
    g_listP[i1 * P_TOT + sl1] = p; g_listW[i1 * P_TOT + sl1] = w1;

    // initialize output with blended biases
    const int ob = b * (NCH * HWSZ) + h * 96 + w;
    const float* eb0 = expert_b + i0 * NCH;
    const float* eb1 = expert_b + i1 * NCH;
#pragma unroll 4
    for (int co = 0; co < NCH; ++co)
        out[ob + co * HWSZ] = w0 * eb0[co] + w1 * eb1[co] + shared_b[co];
}

// ---------------- gathered conv: one (expert, 128-pixel) tile per block ----------------
__global__ __launch_bounds__(256, 2) void conv_kernel(
    const float* __restrict__ x, float* __restrict__ out)
{
    constexpr int KT = 36;                     // 4 ci * 9 taps per chunk
    __shared__ __align__(16) float Xs[KT][128];   // [k][pixel]
    __shared__ __align__(16) float Ws[KT][128];   // [k][cout]
    __shared__ int   pB[128];
    __shared__ float pWt[128];
    __shared__ unsigned char pH[128], pWc[128];

    const int e  = blockIdx.y;
    const int bx = blockIdx.x;
    const int tid = threadIdx.x;

    const int cnt = (e < NE) ? g_cnt[e] : P_TOT;
    if (bx * 128 >= cnt) return;               // uniform early exit (before any sync)

    if (tid < 128) {
        int gi = bx * 128 + tid;
        int p; float wt;
        if (e == NE)      { p = gi; wt = 1.f; }               // shared expert: identity list
        else if (gi < cnt){ p = g_listP[e * P_TOT + gi]; wt = g_listW[e * P_TOT + gi]; }
        else              { p = 0;  wt = 0.f; }                // padded slot
        int b  = p / HWSZ; int r = p - b * HWSZ;
        int hh = r / 96;   int ww = r - hh * 96;
        pB[tid]  = b * (NCH * HWSZ) + r;
        pH[tid]  = (unsigned char)hh;
        pWc[tid] = (unsigned char)ww;
        pWt[tid] = wt;
    }
    __syncthreads();

    const int tx = tid & 15, ty = tid >> 4;    // tx -> 8 couts, ty -> 8 pixels
    ull acc[8][4];
#pragma unroll
    for (int i = 0; i < 8; ++i)
#pragma unroll
        for (int j = 0; j < 4; ++j) acc[i][j] = 0ull;

    for (int c = 0; c < 32; ++c) {             // 32 chunks of 4 ci
        const int ci0 = c * 4;
        __syncthreads();
        // Ws: contiguous slab of pre-transposed weights (coalesced float4)
        {
            const float4* src = (const float4*)(g_wT + (e * KFULL + ci0 * 9) * NCH);
            float4* dst = (float4*)&Ws[0][0];
            for (int i = tid; i < (KT * 128) / 4; i += 256) dst[i] = src[i];
        }
        // Xs: gathered im2col
        for (int i = tid; i < KT * 128; i += 256) {
            int k = i >> 7, m = i & 127;
            int ci = k / 9, tap = k - ci * 9;
            int ky = tap / 3, kx = tap - ky * 3;
            int hh = (int)pH[m] + ky - 1, ww = (int)pWc[m] + kx - 1;
            float v = 0.f;
            if ((unsigned)hh < 96u && (unsigned)ww < 96u)
                v = __ldg(&x[pB[m] + (ci0 + ci) * HWSZ + (ky - 1) * 96 + (kx - 1)]);
            Xs[k][m] = v;
        }
        __syncthreads();
#pragma unroll 6
        for (int k = 0; k < KT; ++k) {
            float4 xa = *(const float4*)&Xs[k][ty * 8];
            float4 xb = *(const float4*)&Xs[k][ty * 8 + 4];
            ull xd[8];
            xd[0] = dup2(xa.x); xd[1] = dup2(xa.y); xd[2] = dup2(xa.z); xd[3] = dup2(xa.w);
            xd[4] = dup2(xb.x); xd[5] = dup2(xb.y); xd[6] = dup2(xb.z); xd[7] = dup2(xb.w);
            const ull* wr = (const ull*)&Ws[k][tx * 8];
            ull w0 = wr[0], w1 = wr[1], w2 = wr[2], w3 = wr[3];
#pragma unroll
            for (int i = 0; i < 8; ++i) {
                acc[i][0] = ffma2(xd[i], w0, acc[i][0]);
                acc[i][1] = ffma2(xd[i], w1, acc[i][1]);
                acc[i][2] = ffma2(xd[i], w2, acc[i][2]);
                acc[i][3] = ffma2(xd[i], w3, acc[i][3]);
            }
        }
    }

    // scatter-accumulate (REDG float adds; padded slots have wt=0)
#pragma unroll
    for (int i = 0; i < 8; ++i) {
        const int m = ty * 8 + i;
        const float wt = pWt[m];
        const int ob = pB[m];
#pragma unroll
        for (int j = 0; j < 4; ++j) {
            float2 v = unpack2(acc[i][j]);
            int co = tx * 8 + j * 2;
            atomicAdd(&out[ob + co * HWSZ],       wt * v.x);
            atomicAdd(&out[ob + (co + 1) * HWSZ], wt * v.y);
        }
    }
}

// ---------------- launch ----------------
extern "C" void kernel_launch(void* const* d_in, const int* in_sizes, int n_in,
                              void* d_out, int out_size) {
    const float* x        = (const float*)d_in[0];
    const float* gate_w   = (const float*)d_in[1];
    const float* gate_b   = (const float*)d_in[2];
    const float* expert_w = (const float*)d_in[3];
    const float* expert_b = (const float*)d_in[4];
    const float* shared_w = (const float*)d_in[5];
    const float* shared_b = (const float*)d_in[6];
    float* out = (float*)d_out;

    prep_kernel<<<(NEXP * KFULL * NCH + 255) / 256, 256>>>(expert_w, shared_w);
    gate_kernel<<<dim3(6, 6, 4), 256>>>(x, gate_w, gate_b, expert_b, shared_b, out);
    conv_kernel<<<dim3(P_TOT / 128, NEXP), 256>>>(x, out);
}

// round 9
// speedup vs baseline: 5.1381x; 5.1381x over previous
#include <cuda_runtime.h>
#include <cuda_fp16.h>
#include <cstdint>

#define HWSZ 9216            // 96*96
#define NCH  128
#define NE   8
#define NEXP 9               // experts + shared
#define P_TOT 36864          // 4*96*96
#define KFULL 1152           // 128*9
#define NKB   18             // K-blocks of 64, tap-major: k = tap*128 + ci

// ---------------- device scratch ----------------
__device__ __half g_xh[(long)P_TOT * NCH];             // x transposed [p][ci], fp16
__device__ __half g_wh[(long)NEXP * NKB * 128 * 64];   // pre-swizzled B tiles, fp16
__device__ float  g_acc[(long)P_TOT * NCH];            // pixel-major accumulator
__device__ int    g_sel01[P_TOT];
__device__ float2 g_w01[P_TOT];
__device__ int    g_listP[NE * P_TOT];
__device__ float  g_listW[NE * P_TOT];
__device__ int    g_cnt[NE];

// ---------------- smem layout (offsets from 1024-aligned base) ----------------
// stage s at s*32768: A tile 16KB (128 rows x 64 k fp16, XOR-swizzled), B tile 16KB
#define SM_SPIX 65536        // 9*128 int
#define SM_PP   70144        // 128 int
#define SM_PW0  70656        // 128 float
#define SMEM_BYTES 72192     // incl. 1KB alignment slack

// ---------------- PTX helpers ----------------
__device__ __forceinline__ uint32_t smem_u32(const void* p) {
    return (uint32_t)__cvta_generic_to_shared(p);
}
__device__ __forceinline__ void cpa16(uint32_t dst, const void* src, int ssz) {
    asm volatile("cp.async.cg.shared.global [%0], [%1], 16, %2;"
                 :: "r"(dst), "l"(src), "r"(ssz) : "memory");
}
__device__ __forceinline__ void cp_commit() {
    asm volatile("cp.async.commit_group;" ::: "memory");
}
__device__ __forceinline__ void ldm4(uint32_t* r, uint32_t addr) {
    asm volatile("ldmatrix.sync.aligned.m8n8.x4.shared.b16 {%0,%1,%2,%3}, [%4];"
                 : "=r"(r[0]), "=r"(r[1]), "=r"(r[2]), "=r"(r[3]) : "r"(addr));
}
__device__ __forceinline__ void mma16816(float* d, const uint32_t* a, const uint32_t* b) {
    asm volatile("mma.sync.aligned.m16n8k16.row.col.f32.f16.f16.f32 "
                 "{%0,%1,%2,%3}, {%4,%5,%6,%7}, {%8,%9}, {%0,%1,%2,%3};"
                 : "+f"(d[0]), "+f"(d[1]), "+f"(d[2]), "+f"(d[3])
                 : "r"(a[0]), "r"(a[1]), "r"(a[2]), "r"(a[3]),
                   "r"(b[0]), "r"(b[1]));
}

// ---------------- prep: fp16 weights, tap-major K-block tiles, pre-swizzled ----------
__global__ void prep_w(const float* __restrict__ expert_w,
                       const float* __restrict__ shared_w) {
    int idx = blockIdx.x * 256 + threadIdx.x;
    if (idx >= NEXP * NKB * 128 * 64) return;
    int c   = idx & 63;            // k within 64-block
    int row = (idx >> 6) & 127;    // cout
    int t2  = idx >> 13;
    int kb  = t2 % NKB;
    int e   = t2 / NKB;
    int tap = kb >> 1;
    int ci  = ((kb & 1) << 6) + c;
    float v = (e < NE) ? expert_w[(((e * NCH + row) * NCH) + ci) * 9 + tap]
                       : shared_w[((row * NCH) + ci) * 9 + tap];
    int chunk = c >> 3, within = c & 7;
    int swc = chunk ^ (row & 7);                    // 16B-chunk XOR swizzle
    g_wh[(long)(e * NKB + kb) * 8192 + row * 64 + swc * 8 + within] = __float2half_rn(v);
}

// ---------------- prep: transpose x to [p][ci] fp16 ----------------
__global__ void prep_x(const float* __restrict__ x) {
    __shared__ float t[32][33];
    const int b = blockIdx.z, ci0 = blockIdx.y * 32, p0 = blockIdx.x * 32;
    const int tx = threadIdx.x, ty = threadIdx.y;   // (32, 8)
#pragma unroll
    for (int j = 0; j < 32; j += 8)
        t[ty + j][tx] = x[(long)(b * NCH + ci0 + ty + j) * HWSZ + p0 + tx];
    __syncthreads();
#pragma unroll
    for (int j = 0; j < 32; j += 8)
        g_xh[(long)(b * HWSZ + p0 + ty + j) * NCH + ci0 + tx] =
            __float2half_rn(t[tx][ty + j]);
}

// ---------------- gate: scores, top-2, softmax -> per-pixel sel/weights -------------
__global__ __launch_bounds__(256) void gate_kernel(
    const float* __restrict__ x, const float* __restrict__ gate_w,
    const float* __restrict__ gate_bias)
{
    __shared__ float gwS[NE * KFULL];
    __shared__ float xt[8 * 18 * 18];
    const int tid = threadIdx.x;
    const int tx = tid & 15, ty = tid >> 4;
    const int bx = blockIdx.x, by = blockIdx.y, b = blockIdx.z;

    for (int i = tid; i < NE * KFULL; i += 256) gwS[i] = gate_w[i];

    float acc[NE];
#pragma unroll
    for (int e = 0; e < NE; ++e) acc[e] = 0.f;

    const int h = by * 16 + ty, w = bx * 16 + tx;
    const float* xb = x + (long)b * (NCH * HWSZ);

    for (int cc = 0; cc < 16; ++cc) {
        __syncthreads();
        for (int i = tid; i < 8 * 324; i += 256) {
            int ci = i / 324; int r = i - ci * 324;
            int ly = r / 18;  int lx = r - ly * 18;
            int gh = by * 16 + ly - 1, gw = bx * 16 + lx - 1;
            float v = 0.f;
            if ((unsigned)gh < 96u && (unsigned)gw < 96u)
                v = xb[(cc * 8 + ci) * HWSZ + gh * 96 + gw];
            xt[i] = v;
        }
        __syncthreads();
#pragma unroll
        for (int ci = 0; ci < 8; ++ci) {
            float xn[9];
            const int base = ci * 324 + ty * 18 + tx;
#pragma unroll
            for (int r = 0; r < 3; ++r)
#pragma unroll
                for (int c2 = 0; c2 < 3; ++c2)
                    xn[r * 3 + c2] = xt[base + r * 18 + c2];
#pragma unroll
            for (int e = 0; e < NE; ++e) {
                const float* wp = &gwS[e * KFULL + (cc * 8 + ci) * 9];
                float a = acc[e];
#pragma unroll
                for (int t = 0; t < 9; ++t) a += wp[t] * xn[t];
                acc[e] = a;
            }
        }
    }

    float s[NE];
    float v0 = -1e30f, v1 = -1e30f; int i0 = 0, i1 = 1;
#pragma unroll
    for (int e = 0; e < NE; ++e) {
        float sv = 1.f / (1.f + expf(-acc[e]));
        s[e] = sv;
        float bv = sv + gate_bias[e];
        if (bv > v0)      { v1 = v0; i1 = i0; v0 = bv; i0 = e; }
        else if (bv > v1) { v1 = bv; i1 = e; }
    }
    float s0 = s[i0], s1 = s[i1];
    float mx = fmaxf(s0, s1);
    float e0 = expf(s0 - mx), e1 = expf(s1 - mx);
    float inv = 1.f / (e0 + e1);

    const int p = b * HWSZ + h * 96 + w;
    g_sel01[p] = i0 | (i1 << 8);
    g_w01[p]   = make_float2(e0 * inv, e1 * inv);
}

// ---------------- deterministic sorted list build (1 block per expert) --------------
__global__ __launch_bounds__(1024) void listbuild() {
    __shared__ int wsum[32];
    __shared__ int woff[33];
    const int e = blockIdx.x;
    const int tid = threadIdx.x, lane = tid & 31, wrp = tid >> 5;
    int base = 0;
    for (int seg = 0; seg < P_TOT / 1024; ++seg) {
        int p = seg * 1024 + tid;
        int s01 = g_sel01[p];
        bool f0 = ((s01 & 255) == e), f1 = ((s01 >> 8) == e);
        bool f = f0 || f1;
        unsigned msk = __ballot_sync(0xFFFFFFFFu, f);
        if (lane == 0) wsum[wrp] = __popc(msk);
        __syncthreads();
        if (tid == 0) {
            int a = 0;
#pragma unroll
            for (int w2 = 0; w2 < 32; ++w2) { woff[w2] = a; a += wsum[w2]; }
            woff[32] = a;
        }
        __syncthreads();
        if (f) {
            float2 ww = g_w01[p];
            int pos = base + woff[wrp] + __popc(msk & ((1u << lane) - 1u));
            g_listP[e * P_TOT + pos] = p;
            g_listW[e * P_TOT + pos] = f0 ? ww.x : ww.y;
        }
        base += woff[32];
        __syncthreads();
    }
    if (tid == 0) g_cnt[e] = base;
}

// ---------------- stage fill: gathered A + pre-swizzled B (fp16) --------------------
__device__ __forceinline__ void fill_stage(int tid, uint32_t bb, int kb, int e,
                                           const int* SPIX) {
    const int tap  = kb >> 1;
    const int ci0b = ((kb & 1) << 6) * 2;          // byte offset within pixel row
    const char* xs = (const char*)g_xh;
    for (int i = tid; i < 1024; i += 256) {         // A: 128 rows x 8 chunks
        int r = i >> 3, cc = i & 7;
        int sp = SPIX[tap * 128 + r];
        uint32_t dst = bb + (uint32_t)(r * 128 + ((cc ^ (r & 7)) << 4));
        const char* src = xs + (long)(sp < 0 ? 0 : sp) * 256 + ci0b + cc * 16;
        cpa16(dst, src, sp < 0 ? 0 : 16);
    }
    const char* ws = (const char*)g_wh;
    const long wb = (long)(e * NKB + kb) * 16384;
    for (int i = tid; i < 1024; i += 256)           // B: plain slab copy
        cpa16(bb + 16384u + (uint32_t)i * 16, ws + wb + (long)i * 16, 16);
    cp_commit();
}

// ---------------- mma.sync conv: one (expert, 128-pixel, 128-cout) tile per CTA -----
// SHARED: plain-store (initializes g_acc). else: coalesced atomicAdd of w0 * acc.
template <bool SHARED>
__global__ __launch_bounds__(256, 2) void conv_mma()
{
    extern __shared__ char dsm[];
    char* SB = (char*)(((uintptr_t)dsm + 1023) & ~(uintptr_t)1023);
    const uint32_t sb32 = smem_u32(SB);

    int*   SPIX = (int*)(SB + SM_SPIX);
    int*   PP   = (int*)(SB + SM_PP);
    float* PW0  = (float*)(SB + SM_PW0);

    const int tid  = threadIdx.x;
    const int lane = tid & 31;
    const int wid  = tid >> 5;
    const int bx   = blockIdx.x;
    const int e    = SHARED ? NE : blockIdx.y;
    const int cnt  = SHARED ? P_TOT : g_cnt[e];
    if (!SHARED && bx * 128 >= cnt) return;         // uniform exit, before any sync

    if (tid < 128) {
        int gi = bx * 128 + tid;
        int p = 0; float w0 = 0.f;
        if (SHARED) { p = gi; w0 = 1.f; }
        else if (gi < cnt) {
            p = g_listP[e * P_TOT + gi];
            w0 = g_listW[e * P_TOT + gi];
        }
        PP[tid]  = p;
        PW0[tid] = w0;
    }
    __syncthreads();

    for (int i = tid; i < 9 * 128; i += 256) {
        int tap = i >> 7, m = i & 127;
        int p = PP[m];
        int b = p / HWSZ, r = p - b * HWSZ;
        int h = r / 96, w = r - h * 96;
        int hh = h + tap / 3 - 1, ww = w + tap % 3 - 1;
        SPIX[i] = ((unsigned)hh < 96u && (unsigned)ww < 96u)
                      ? b * HWSZ + hh * 96 + ww : -1;
    }
    __syncthreads();

    fill_stage(tid, sb32, 0, e, SPIX);
    fill_stage(tid, sb32 + 32768u, 1, e, SPIX);

    // warp tile: m32 x n64
    const int m0 = (wid & 3) * 32;
    const int n0 = (wid >> 2) * 64;
    const int j  = lane >> 3, r8 = lane & 7;

    float acc[2][8][4];
#pragma unroll
    for (int a = 0; a < 2; ++a)
#pragma unroll
        for (int b = 0; b < 8; ++b)
#pragma unroll
            for (int c = 0; c < 4; ++c) acc[a][b][c] = 0.f;

    for (int kb = 0; kb < NKB; ++kb) {
        if (kb < NKB - 1) asm volatile("cp.async.wait_group 1;" ::: "memory");
        else              asm volatile("cp.async.wait_group 0;" ::: "memory");
        __syncthreads();
        const uint32_t aS = sb32 + (uint32_t)(kb & 1) * 32768u;
        const uint32_t bS = aS + 16384u;
#pragma unroll
        for (int ks = 0; ks < 4; ++ks) {
            uint32_t afr[2][4], bfr[4][4];
#pragma unroll
            for (int mt = 0; mt < 2; ++mt) {
                int row = m0 + mt * 16 + ((j & 1) << 3) + r8;
                int cc  = (ks << 1) + (j >> 1);
                ldm4(afr[mt], aS + row * 128 + ((cc ^ (row & 7)) << 4));
            }
#pragma unroll
            for (int np = 0; np < 4; ++np) {
                int row = n0 + np * 16 + ((j >> 1) << 3) + r8;
                int cc  = (ks << 1) + (j & 1);
                ldm4(bfr[np], bS + row * 128 + ((cc ^ (row & 7)) << 4));
            }
#pragma unroll
            for (int mt = 0; mt < 2; ++mt)
#pragma unroll
                for (int nn = 0; nn < 8; ++nn)
                    mma16816(acc[mt][nn], afr[mt], &bfr[nn >> 1][(nn & 1) * 2]);
        }
        __syncthreads();
        if (kb + 2 < NKB) fill_stage(tid, sb32 + (uint32_t)(kb & 1) * 32768u,
                                     kb + 2, e, SPIX);
    }

    // epilogue into pixel-major scratch: D frag map c0,c1 -> row=lr; c2,c3 -> row=lr+8
    const int lr = lane >> 2, lc = (lane & 3) * 2;
#pragma unroll
    for (int mt = 0; mt < 2; ++mt) {
#pragma unroll
        for (int hf = 0; hf < 2; ++hf) {
            const int row = m0 + mt * 16 + hf * 8 + lr;
            const long ob = (long)PP[row] * NCH;
            const float w0 = PW0[row];
            if (SHARED) {
#pragma unroll
                for (int nn = 0; nn < 8; ++nn) {
                    int co = n0 + nn * 8 + lc;
                    *(float2*)&g_acc[ob + co] =
                        make_float2(acc[mt][nn][hf * 2], acc[mt][nn][hf * 2 + 1]);
                }
            } else if (w0 != 0.f) {
#pragma unroll
                for (int nn = 0; nn < 8; ++nn) {
                    int co = n0 + nn * 8 + lc;
                    atomicAdd(&g_acc[ob + co],     w0 * acc[mt][nn][hf * 2]);
                    atomicAdd(&g_acc[ob + co + 1], w0 * acc[mt][nn][hf * 2 + 1]);
                }
            }
        }
    }
}

// ---------------- finalize: transpose scratch to NCHW + fold all biases -------------
__global__ void finalize(const float* __restrict__ expert_b,
                         const float* __restrict__ shared_b,
                         float* __restrict__ out) {
    __shared__ float t[32][33];
    __shared__ float EBS[NE * 132];
    __shared__ float SBS[NCH];
    const int b = blockIdx.z, co0 = blockIdx.y * 32, p0 = blockIdx.x * 32;
    const int tx = threadIdx.x, ty = threadIdx.y;   // (32, 8)
    const int tid = ty * 32 + tx;
    for (int i = tid; i < NE * NCH; i += 256)
        EBS[(i >> 7) * 132 + (i & 127)] = expert_b[i];
    for (int i = tid; i < NCH; i += 256) SBS[i] = shared_b[i];
#pragma unroll
    for (int j = 0; j < 32; j += 8)
        t[ty + j][tx] = g_acc[(long)(b * HWSZ + p0 + ty + j) * NCH + co0 + tx];
    __syncthreads();
    const int p = b * HWSZ + p0 + tx;
    const int s = g_sel01[p];
    const float2 w = g_w01[p];
    const float* b0 = &EBS[(s & 255) * 132];
    const float* b1 = &EBS[(s >> 8) * 132];
#pragma unroll
    for (int j = 0; j < 32; j += 8) {
        int co = co0 + ty + j;
        out[(long)(b * NCH + co) * HWSZ + p0 + tx] =
            t[tx][ty + j] + SBS[co] + w.x * b0[co] + w.y * b1[co];
    }
}

// ---------------- launch ----------------
extern "C" void kernel_launch(void* const* d_in, const int* in_sizes, int n_in,
                              void* d_out, int out_size) {
    const float* x        = (const float*)d_in[0];
    const float* gate_w   = (const float*)d_in[1];
    const float* gate_b   = (const float*)d_in[2];
    const float* expert_w = (const float*)d_in[3];
    const float* expert_b = (const float*)d_in[4];
    const float* shared_w = (const float*)d_in[5];
    const float* shared_b = (const float*)d_in[6];
    float* out = (float*)d_out;

    cudaFuncSetAttribute(conv_mma<true>,
                         cudaFuncAttributeMaxDynamicSharedMemorySize, SMEM_BYTES);
    cudaFuncSetAttribute(conv_mma<false>,
                         cudaFuncAttributeMaxDynamicSharedMemorySize, SMEM_BYTES);

    prep_w<<<(NEXP * NKB * 128 * 64 + 255) / 256, 256>>>(expert_w, shared_w);
    prep_x<<<dim3(HWSZ / 32, NCH / 32, 4), dim3(32, 8)>>>(x);
    gate_kernel<<<dim3(6, 6, 4), 256>>>(x, gate_w, gate_b);
    listbuild<<<NE, 1024>>>();
    conv_mma<true><<<P_TOT / 128, 256, SMEM_BYTES>>>();                 // shared expert
    conv_mma<false><<<dim3(P_TOT / 128, NE), 256, SMEM_BYTES>>>();      // routed experts
    finalize<<<dim3(HWSZ / 32, NCH / 32, 4), dim3(32, 8)>>>(expert_b, shared_b, out);
}

// round 10
// speedup vs baseline: 6.9811x; 1.3587x over previous
#include <cuda_runtime.h>
#include <cuda_fp16.h>
#include <cstdint>

#define HWSZ 9216            // 96*96
#define NCH  128
#define NE   8
#define P_TOT 36864          // 4*96*96
#define KFULL 1152           // 128*9
#define NKB   18             // K-blocks of 64, tap-major: k = tap*128 + ci
#define NPART 32
#define PPP   (P_TOT / NPART)   // 1152 pixels per part

// ---------------- device scratch ----------------
__device__ __half g_xh[(long)P_TOT * NCH];             // x transposed [p][ci], fp16
__device__ __half g_wh[(long)NE * NKB * 128 * 64];     // merged (We+Wsh) B tiles, fp16
__device__ float  g_acc[(long)P_TOT * NCH];            // pixel-major accumulator
__device__ int    g_sel01[P_TOT];
__device__ float2 g_w01[P_TOT];
__device__ int    g_listP[NE * P_TOT];
__device__ float  g_listW[NE * P_TOT];
__device__ int    g_cnt[NE];
__device__ int    g_pcnt[NE * NPART];

// ---------------- smem layout (offsets from 1024-aligned base) ----------------
#define SM_SPIX 65536        // 9*128 int
#define SM_PP   70144        // 128 int
#define SM_PW0  70656        // 128 float
#define SMEM_BYTES 72192

// ---------------- PTX helpers ----------------
__device__ __forceinline__ uint32_t smem_u32(const void* p) {
    return (uint32_t)__cvta_generic_to_shared(p);
}
__device__ __forceinline__ void cpa16(uint32_t dst, const void* src, int ssz) {
    asm volatile("cp.async.cg.shared.global [%0], [%1], 16, %2;"
                 :: "r"(dst), "l"(src), "r"(ssz) : "memory");
}
__device__ __forceinline__ void cp_commit() {
    asm volatile("cp.async.commit_group;" ::: "memory");
}
__device__ __forceinline__ void ldm4(uint32_t* r, uint32_t addr) {
    asm volatile("ldmatrix.sync.aligned.m8n8.x4.shared.b16 {%0,%1,%2,%3}, [%4];"
                 : "=r"(r[0]), "=r"(r[1]), "=r"(r[2]), "=r"(r[3]) : "r"(addr));
}
__device__ __forceinline__ void mma16816(float* d, const uint32_t* a, const uint32_t* b) {
    asm volatile("mma.sync.aligned.m16n8k16.row.col.f32.f16.f16.f32 "
                 "{%0,%1,%2,%3}, {%4,%5,%6,%7}, {%8,%9}, {%0,%1,%2,%3};"
                 : "+f"(d[0]), "+f"(d[1]), "+f"(d[2]), "+f"(d[3])
                 : "r"(a[0]), "r"(a[1]), "r"(a[2]), "r"(a[3]),
                   "r"(b[0]), "r"(b[1]));
}

// ---------------- prep: merged fp16 weights (We + Wsh), pre-swizzled ----------------
__global__ void prep_w(const float* __restrict__ expert_w,
                       const float* __restrict__ shared_w) {
    int idx = blockIdx.x * 256 + threadIdx.x;
    if (idx >= NE * NKB * 128 * 64) return;
    int c   = idx & 63;            // k within 64-block
    int row = (idx >> 6) & 127;    // cout
    int t2  = idx >> 13;
    int kb  = t2 % NKB;
    int e   = t2 / NKB;
    int tap = kb >> 1;
    int ci  = ((kb & 1) << 6) + c;
    float v = expert_w[(((e * NCH + row) * NCH) + ci) * 9 + tap]
            + shared_w[((row * NCH) + ci) * 9 + tap];
    int chunk = c >> 3, within = c & 7;
    int swc = chunk ^ (row & 7);                    // 16B-chunk XOR swizzle
    g_wh[(long)(e * NKB + kb) * 8192 + row * 64 + swc * 8 + within] = __float2half_rn(v);
}

// ---------------- prep: transpose x to [p][ci] fp16 + zero g_acc --------------------
__global__ void prep_x(const float* __restrict__ x) {
    __shared__ float t[32][33];
    const int b = blockIdx.z, ci0 = blockIdx.y * 32, p0 = blockIdx.x * 32;
    const int tx = threadIdx.x, ty = threadIdx.y;   // (32, 8)
    const int tid = ty * 32 + tx;
#pragma unroll
    for (int j = 0; j < 32; j += 8)
        t[ty + j][tx] = x[(long)(b * NCH + ci0 + ty + j) * HWSZ + p0 + tx];
    // zero the matching [p0..+32)[ci0..+32) slice of g_acc (covers it exactly)
    {
        int row = tid >> 3, cg = tid & 7;
        *(float4*)&g_acc[(long)(b * HWSZ + p0 + row) * NCH + ci0 + cg * 4] =
            make_float4(0.f, 0.f, 0.f, 0.f);
    }
    __syncthreads();
#pragma unroll
    for (int j = 0; j < 32; j += 8)
        g_xh[(long)(b * HWSZ + p0 + ty + j) * NCH + ci0 + tx] =
            __float2half_rn(t[tx][ty + j]);
}

// ---------------- gate: scores, top-2, softmax -> per-pixel sel/weights -------------
__global__ __launch_bounds__(256) void gate_kernel(
    const float* __restrict__ x, const float* __restrict__ gate_w,
    const float* __restrict__ gate_bias)
{
    __shared__ float gwS[NE * KFULL];
    __shared__ float xt[8 * 18 * 18];
    const int tid = threadIdx.x;
    const int tx = tid & 15, ty = tid >> 4;
    const int bx = blockIdx.x, by = blockIdx.y, b = blockIdx.z;

    for (int i = tid; i < NE * KFULL; i += 256) gwS[i] = gate_w[i];

    float acc[NE];
#pragma unroll
    for (int e = 0; e < NE; ++e) acc[e] = 0.f;

    const int h = by * 16 + ty, w = bx * 16 + tx;
    const float* xb = x + (long)b * (NCH * HWSZ);

    for (int cc = 0; cc < 16; ++cc) {
        __syncthreads();
        for (int i = tid; i < 8 * 324; i += 256) {
            int ci = i / 324; int r = i - ci * 324;
            int ly = r / 18;  int lx = r - ly * 18;
            int gh = by * 16 + ly - 1, gw = bx * 16 + lx - 1;
            float v = 0.f;
            if ((unsigned)gh < 96u && (unsigned)gw < 96u)
                v = xb[(cc * 8 + ci) * HWSZ + gh * 96 + gw];
            xt[i] = v;
        }
        __syncthreads();
#pragma unroll
        for (int ci = 0; ci < 8; ++ci) {
            float xn[9];
            const int base = ci * 324 + ty * 18 + tx;
#pragma unroll
            for (int r = 0; r < 3; ++r)
#pragma unroll
                for (int c2 = 0; c2 < 3; ++c2)
                    xn[r * 3 + c2] = xt[base + r * 18 + c2];
#pragma unroll
            for (int e = 0; e < NE; ++e) {
                const float* wp = &gwS[e * KFULL + (cc * 8 + ci) * 9];
                float a = acc[e];
#pragma unroll
                for (int t = 0; t < 9; ++t) a += wp[t] * xn[t];
                acc[e] = a;
            }
        }
    }

    float s[NE];
    float v0 = -1e30f, v1 = -1e30f; int i0 = 0, i1 = 1;
#pragma unroll
    for (int e = 0; e < NE; ++e) {
        float sv = 1.f / (1.f + expf(-acc[e]));
        s[e] = sv;
        float bv = sv + gate_bias[e];
        if (bv > v0)      { v1 = v0; i1 = i0; v0 = bv; i0 = e; }
        else if (bv > v1) { v1 = bv; i1 = e; }
    }
    float s0 = s[i0], s1 = s[i1];
    float mx = fmaxf(s0, s1);
    float e0 = expf(s0 - mx), e1 = expf(s1 - mx);
    float inv = 1.f / (e0 + e1);

    const int p = b * HWSZ + h * 96 + w;
    g_sel01[p] = i0 | (i1 << 8);
    g_w01[p]   = make_float2(e0 * inv, e1 * inv);
}

// ---------------- parallel deterministic list build --------------------------------
// pass 1: per-(part) expert counts via warp ballots
__global__ __launch_bounds__(1024) void list_count() {
    __shared__ int wc[32][8];
    const int part = blockIdx.x;
    const int tid = threadIdx.x, lane = tid & 31, wrp = tid >> 5;
    int cnt = 0;                                   // lane<8: count for expert==lane
#pragma unroll
    for (int seg = 0; seg < 2; ++seg) {
        int off = seg * 1024 + tid;
        bool valid = off < PPP;
        int s01 = valid ? g_sel01[part * PPP + off] : 0x0F0F;   // no-match sentinel
#pragma unroll
        for (int e = 0; e < NE; ++e) {
            unsigned m0 = __ballot_sync(0xFFFFFFFFu, (s01 & 255) == e);
            unsigned m1 = __ballot_sync(0xFFFFFFFFu, (s01 >> 8) == e);
            if (lane == e) cnt += __popc(m0) + __popc(m1);
        }
    }
    if (lane < 8) wc[wrp][lane] = cnt;
    __syncthreads();
    if (tid < 8) {
        int a = 0;
#pragma unroll
        for (int w2 = 0; w2 < 32; ++w2) a += wc[w2][tid];
        g_pcnt[tid * NPART + part] = a;
    }
}

// pass 2: deterministic scatter; block (part, e)
__global__ __launch_bounds__(1024) void list_scatter() {
    __shared__ int wsum[32];
    __shared__ int woff[33];
    __shared__ int sbase;
    const int part = blockIdx.x, e = blockIdx.y;
    const int tid = threadIdx.x, lane = tid & 31, wrp = tid >> 5;
    if (tid == 0) {
        int a = 0, tot = 0;
#pragma unroll
        for (int p2 = 0; p2 < NPART; ++p2) {
            int c = g_pcnt[e * NPART + p2];
            if (p2 < part) a += c;
            tot += c;
        }
        sbase = a;
        if (part == 0) g_cnt[e] = tot;
    }
    __syncthreads();
    int base = sbase;
#pragma unroll
    for (int seg = 0; seg < 2; ++seg) {
        int off = seg * 1024 + tid;
        bool valid = off < PPP;
        int p = part * PPP + off;
        int s01 = valid ? g_sel01[p] : 0x0F0F;
        bool f0 = ((s01 & 255) == e), f1 = ((s01 >> 8) == e);
        bool f = f0 || f1;
        unsigned msk = __ballot_sync(0xFFFFFFFFu, f);
        if (lane == 0) wsum[wrp] = __popc(msk);
        __syncthreads();
        if (tid == 0) {
            int a = 0;
#pragma unroll
            for (int w2 = 0; w2 < 32; ++w2) { woff[w2] = a; a += wsum[w2]; }
            woff[32] = a;
        }
        __syncthreads();
        if (f) {
            float2 ww = g_w01[p];
            int pos = base + woff[wrp] + __popc(msk & ((1u << lane) - 1u));
            g_listP[e * P_TOT + pos] = p;
            g_listW[e * P_TOT + pos] = f0 ? ww.x : ww.y;
        }
        base += woff[32];
        __syncthreads();
    }
}

// ---------------- stage fill: gathered A + pre-swizzled B (fp16) --------------------
__device__ __forceinline__ void fill_stage(int tid, uint32_t bb, int kb, int e,
                                           const int* SPIX) {
    const int tap  = kb >> 1;
    const int ci0b = ((kb & 1) << 6) * 2;
    const char* xs = (const char*)g_xh;
    for (int i = tid; i < 1024; i += 256) {         // A: 128 rows x 8 chunks
        int r = i >> 3, cc = i & 7;
        int sp = SPIX[tap * 128 + r];
        uint32_t dst = bb + (uint32_t)(r * 128 + ((cc ^ (r & 7)) << 4));
        const char* src = xs + (long)(sp < 0 ? 0 : sp) * 256 + ci0b + cc * 16;
        cpa16(dst, src, sp < 0 ? 0 : 16);
    }
    const char* ws = (const char*)g_wh;
    const long wb = (long)(e * NKB + kb) * 16384;
    for (int i = tid; i < 1024; i += 256)           // B: plain slab copy
        cpa16(bb + 16384u + (uint32_t)i * 16, ws + wb + (long)i * 16, 16);
    cp_commit();
}

// ---------------- mma.sync conv: one (expert, 128-pixel, 128-cout) tile per CTA -----
__global__ __launch_bounds__(256, 2) void conv_mma()
{
    extern __shared__ char dsm[];
    char* SB = (char*)(((uintptr_t)dsm + 1023) & ~(uintptr_t)1023);
    const uint32_t sb32 = smem_u32(SB);

    int*   SPIX = (int*)(SB + SM_SPIX);
    int*   PP   = (int*)(SB + SM_PP);
    float* PW0  = (float*)(SB + SM_PW0);

    const int tid  = threadIdx.x;
    const int lane = tid & 31;
    const int wid  = tid >> 5;
    const int bx   = blockIdx.x;
    const int e    = blockIdx.y;
    const int cnt  = g_cnt[e];
    if (bx * 128 >= cnt) return;                    // uniform exit, before any sync

    if (tid < 128) {
        int gi = bx * 128 + tid;
        int p = 0; float w0 = 0.f;
        if (gi < cnt) {
            p = g_listP[e * P_TOT + gi];
            w0 = g_listW[e * P_TOT + gi];
        }
        PP[tid]  = p;
        PW0[tid] = w0;
    }
    __syncthreads();

    for (int i = tid; i < 9 * 128; i += 256) {
        int tap = i >> 7, m = i & 127;
        int p = PP[m];
        int b = p / HWSZ, r = p - b * HWSZ;
        int h = r / 96, w = r - h * 96;
        int hh = h + tap / 3 - 1, ww = w + tap % 3 - 1;
        SPIX[i] = ((unsigned)hh < 96u && (unsigned)ww < 96u)
                      ? b * HWSZ + hh * 96 + ww : -1;
    }
    __syncthreads();

    fill_stage(tid, sb32, 0, e, SPIX);
    fill_stage(tid, sb32 + 32768u, 1, e, SPIX);

    // warp tile: m32 x n64
    const int m0 = (wid & 3) * 32;
    const int n0 = (wid >> 2) * 64;
    const int j  = lane >> 3, r8 = lane & 7;

    float acc[2][8][4];
#pragma unroll
    for (int a = 0; a < 2; ++a)
#pragma unroll
        for (int b = 0; b < 8; ++b)
#pragma unroll
            for (int c = 0; c < 4; ++c) acc[a][b][c] = 0.f;

    for (int kb = 0; kb < NKB; ++kb) {
        if (kb < NKB - 1) asm volatile("cp.async.wait_group 1;" ::: "memory");
        else              asm volatile("cp.async.wait_group 0;" ::: "memory");
        __syncthreads();
        const uint32_t aS = sb32 + (uint32_t)(kb & 1) * 32768u;
        const uint32_t bS = aS + 16384u;
#pragma unroll
        for (int ks = 0; ks < 4; ++ks) {
            uint32_t afr[2][4], bfr[4][4];
#pragma unroll
            for (int mt = 0; mt < 2; ++mt) {
                int row = m0 + mt * 16 + ((j & 1) << 3) + r8;
                int cc  = (ks << 1) + (j >> 1);
                ldm4(afr[mt], aS + row * 128 + ((cc ^ (row & 7)) << 4));
            }
#pragma unroll
            for (int np = 0; np < 4; ++np) {
                int row = n0 + np * 16 + ((j >> 1) << 3) + r8;
                int cc  = (ks << 1) + (j & 1);
                ldm4(bfr[np], bS + row * 128 + ((cc ^ (row & 7)) << 4));
            }
#pragma unroll
            for (int mt = 0; mt < 2; ++mt)
#pragma unroll
                for (int nn = 0; nn < 8; ++nn)
                    mma16816(acc[mt][nn], afr[mt], &bfr[nn >> 1][(nn & 1) * 2]);
        }
        __syncthreads();
        if (kb + 2 < NKB) fill_stage(tid, sb32 + (uint32_t)(kb & 1) * 32768u,
                                     kb + 2, e, SPIX);
    }

    // epilogue: coalesced atomics into pixel-major scratch
    const int lr = lane >> 2, lc = (lane & 3) * 2;
#pragma unroll
    for (int mt = 0; mt < 2; ++mt) {
#pragma unroll
        for (int hf = 0; hf < 2; ++hf) {
            const int row = m0 + mt * 16 + hf * 8 + lr;
            const long ob = (long)PP[row] * NCH;
            const float w0 = PW0[row];
            if (w0 != 0.f) {
#pragma unroll
                for (int nn = 0; nn < 8; ++nn) {
                    int co = n0 + nn * 8 + lc;
                    atomicAdd(&g_acc[ob + co],     w0 * acc[mt][nn][hf * 2]);
                    atomicAdd(&g_acc[ob + co + 1], w0 * acc[mt][nn][hf * 2 + 1]);
                }
            }
        }
    }
}

// ---------------- finalize: transpose scratch to NCHW + fold all biases -------------
__global__ void finalize(const float* __restrict__ expert_b,
                         const float* __restrict__ shared_b,
                         float* __restrict__ out) {
    __shared__ float t[32][33];
    __shared__ float EBS[NE * 132];
    __shared__ float SBS[NCH];
    const int b = blockIdx.z, co0 = blockIdx.y * 32, p0 = blockIdx.x * 32;
    const int tx = threadIdx.x, ty = threadIdx.y;   // (32, 8)
    const int tid = ty * 32 + tx;
    for (int i = tid; i < NE * NCH; i += 256)
        EBS[(i >> 7) * 132 + (i & 127)] = expert_b[i];
    for (int i = tid; i < NCH; i += 256) SBS[i] = shared_b[i];
#pragma unroll
    for (int j = 0; j < 32; j += 8)
        t[ty + j][tx] = g_acc[(long)(b * HWSZ + p0 + ty + j) * NCH + co0 + tx];
    __syncthreads();
    const int p = b * HWSZ + p0 + tx;
    const int s = g_sel01[p];
    const float2 w = g_w01[p];
    const float* b0 = &EBS[(s & 255) * 132];
    const float* b1 = &EBS[(s >> 8) * 132];
#pragma unroll
    for (int j = 0; j < 32; j += 8) {
        int co = co0 + ty + j;
        out[(long)(b * NCH + co) * HWSZ + p0 + tx] =
            t[tx][ty + j] + SBS[co] + w.x * b0[co] + w.y * b1[co];
    }
}

// ---------------- launch ----------------
extern "C" void kernel_launch(void* const* d_in, const int* in_sizes, int n_in,
                              void* d_out, int out_size) {
    const float* x        = (const float*)d_in[0];
    const float* gate_w   = (const float*)d_in[1];
    const float* gate_b   = (const float*)d_in[2];
    const float* expert_w = (const float*)d_in[3];
    const float* expert_b = (const float*)d_in[4];
    const float* shared_w = (const float*)d_in[5];
    const float* shared_b = (const float*)d_in[6];
    float* out = (float*)d_out;

    cudaFuncSetAttribute(conv_mma,
                         cudaFuncAttributeMaxDynamicSharedMemorySize, SMEM_BYTES);

    prep_w<<<(NE * NKB * 128 * 64 + 255) / 256, 256>>>(expert_w, shared_w);
    prep_x<<<dim3(HWSZ / 32, NCH / 32, 4), dim3(32, 8)>>>(x);
    gate_kernel<<<dim3(6, 6, 4), 256>>>(x, gate_w, gate_b);
    list_count<<<NPART, 1024>>>();
    list_scatter<<<dim3(NPART, NE), 1024>>>();
    conv_mma<<<dim3(P_TOT / 128, NE), 256, SMEM_BYTES>>>();
    finalize<<<dim3(HWSZ / 32, NCH / 32, 4), dim3(32, 8)>>>(expert_b, shared_b, out);
}